// round 7
// baseline (speedup 1.0000x reference)
#include <cuda_runtime.h>

#define B 256
#define R 1152
#define C 10
#define O 16
#define I 8
#define K9 (R * I)      // 9216
#define N160 (C * O)    // 160
#define NKS 64          // K-split for gemm1
#define KC (K9 / NKS)   // 144

typedef unsigned long long u64;

__device__ __forceinline__ u64 pk(float lo, float hi) {
    u64 r; asm("mov.b64 %0, {%1, %2};" : "=l"(r) : "f"(lo), "f"(hi)); return r;
}
__device__ __forceinline__ u64 pk1(float v) {
    u64 r; asm("mov.b64 %0, {%1, %1};" : "=l"(r) : "f"(v)); return r;
}
__device__ __forceinline__ void fma2(u64& d, u64 a, u64 b) {
    asm("fma.rn.f32x2 %0, %1, %2, %3;" : "=l"(d) : "l"(a), "l"(b), "l"(d));
}
__device__ __forceinline__ float2 up(u64 v) {
    float2 r; asm("mov.b64 {%0, %1}, %2;" : "=f"(r.x), "=f"(r.y) : "l"(v)); return r;
}

__device__ float g_b[R * C];
__device__ float g_c[R * C];
__device__ float g_xT[K9 * B];           // xT[k][b]
__device__ float g_Wc[K9 * N160];        // Wc[k][n] = c[r,cap]*W[r,cap,o,i], k=r*8+i, n=cap*16+o
__device__ float g_v[B * N160];          // v[b][n]
__device__ float g_spart[NKS * B * N160];

__global__ void init_k() {
    int i = blockIdx.x * blockDim.x + threadIdx.x;
    if (i < R * C) g_b[i] = 0.0f;
}

// x (B x K9) -> g_xT (K9 x B), tiled transpose
__global__ void transpose_k(const float* __restrict__ x) {
    __shared__ float sm[32][33];
    const int k0 = blockIdx.x * 32, b0 = blockIdx.y * 32;
    const int tx = threadIdx.x, ty = threadIdx.y;
#pragma unroll
    for (int j = 0; j < 32; j += 8)
        sm[ty + j][tx] = x[(size_t)(b0 + ty + j) * K9 + k0 + tx];
    __syncthreads();
#pragma unroll
    for (int j = 0; j < 32; j += 8)
        g_xT[(size_t)(k0 + ty + j) * B + b0 + tx] = sm[tx][ty + j];
}

// softmax over routes (axis r) per capsule c. One block per c.
__global__ void softmax_k() {
    const int c = blockIdx.x;
    const int tid = threadIdx.x;
    __shared__ float sm[128];

    float m = -1e30f;
    for (int r = tid; r < R; r += 128) m = fmaxf(m, g_b[r * C + c]);
    sm[tid] = m;
    __syncthreads();
    for (int s = 64; s > 0; s >>= 1) {
        if (tid < s) sm[tid] = fmaxf(sm[tid], sm[tid + s]);
        __syncthreads();
    }
    m = sm[0];
    __syncthreads();

    float sum = 0.0f;
    for (int r = tid; r < R; r += 128) sum += expf(g_b[r * C + c] - m);
    sm[tid] = sum;
    __syncthreads();
    for (int s = 64; s > 0; s >>= 1) {
        if (tid < s) sm[tid] += sm[tid + s];
        __syncthreads();
    }
    float inv = 1.0f / sm[0];

    for (int r = tid; r < R; r += 128)
        g_c[r * C + c] = expf(g_b[r * C + c] - m) * inv;
}

// Wc[k=(r,i)][n=(c,o)] = c[r,c] * W[r,c,o,i]. One block per route r.
__global__ void __launch_bounds__(256) scale_k(const float* __restrict__ W, int uniform) {
    const int r = blockIdx.x;
    const int tid = threadIdx.x;
    __shared__ float wsm[O * I * C];  // 1280: layout (c,o,i)
    __shared__ float csm[C];

    for (int idx = tid; idx < 1280; idx += 256)
        wsm[idx] = W[(size_t)r * 1280 + idx];
    if (tid < C) csm[tid] = uniform ? (1.0f / (float)R) : g_c[r * C + tid];
    __syncthreads();

    for (int idx = tid; idx < 1280; idx += 256) {
        int i = idx / N160;        // 0..7
        int n = idx - i * N160;    // 0..159
        int c = n >> 4;
        g_Wc[(size_t)r * 1280 + idx] = csm[c] * wsm[n * I + i];
    }
}

// GEMM1 partials: spart[ks][b][n] = sum_{k in chunk} xT[k][b] * Wc[k][n]
// tile 128(b) x 32(n), 128 threads, 8x4 per thread via FFMA2. grid (2, 5, NKS).
__global__ void __launch_bounds__(128) gemm1_k() {
    const int b0 = blockIdx.x * 128, n0 = blockIdx.y * 32;
    const int k0 = blockIdx.z * KC;
    const int tid = threadIdx.x;
    const int tn = tid & 7, tm = tid >> 3;  // tn 0..7 (n), tm 0..15 (b)

    __shared__ float xs[16][128];
    __shared__ float ws[16][32];
    u64 acc2[4][4];
#pragma unroll
    for (int p = 0; p < 4; p++)
#pragma unroll
        for (int l = 0; l < 4; l++) acc2[p][l] = 0ull;

    for (int step = 0; step < KC / 16; step++) {
        const int kb = k0 + step * 16;
#pragma unroll
        for (int j = 0; j < 4; j++) {
            int idx4 = tid + j * 128;            // 0..511
            int row = idx4 >> 5, col4 = idx4 & 31;
            *(float4*)&xs[row][col4 * 4] =
                *(const float4*)(g_xT + (size_t)(kb + row) * B + b0 + col4 * 4);
        }
        {
            int row = tid >> 3, col4 = tid & 7;
            *(float4*)&ws[row][col4 * 4] =
                *(const float4*)(g_Wc + (size_t)(kb + row) * N160 + n0 + col4 * 4);
        }
        __syncthreads();
#pragma unroll
        for (int kk = 0; kk < 16; kk++) {
            float4 x0 = *(float4*)&xs[kk][tm * 8];
            float4 x1 = *(float4*)&xs[kk][tm * 8 + 4];
            float4 w0 = *(float4*)&ws[kk][tn * 4];
            u64 xp[4] = {pk(x0.x, x0.y), pk(x0.z, x0.w),
                         pk(x1.x, x1.y), pk(x1.z, x1.w)};
            u64 wr[4] = {pk1(w0.x), pk1(w0.y), pk1(w0.z), pk1(w0.w)};
#pragma unroll
            for (int p = 0; p < 4; p++)
#pragma unroll
                for (int l = 0; l < 4; l++)
                    fma2(acc2[p][l], xp[p], wr[l]);
        }
        __syncthreads();
    }

    float* sp = g_spart + (size_t)blockIdx.z * (B * N160);
#pragma unroll
    for (int p = 0; p < 4; p++) {
        float2 c0 = up(acc2[p][0]), c1 = up(acc2[p][1]);
        float2 c2 = up(acc2[p][2]), c3 = up(acc2[p][3]);
        *(float4*)&sp[(size_t)(b0 + tm * 8 + 2 * p) * N160 + n0 + tn * 4] =
            make_float4(c0.x, c1.x, c2.x, c3.x);
        *(float4*)&sp[(size_t)(b0 + tm * 8 + 2 * p + 1) * N160 + n0 + tn * 4] =
            make_float4(c0.y, c1.y, c2.y, c3.y);
    }
}

// reduce partials + squash. v = s*|s|/(1+s^2). float4-vectorized.
__global__ void squash_k(float* __restrict__ out) {
    const int idx = blockIdx.x * 256 + threadIdx.x;  // < 10240 float4s
    const float4* sp = (const float4*)g_spart;
    float4 s = make_float4(0.f, 0.f, 0.f, 0.f);
#pragma unroll 8
    for (int ks = 0; ks < NKS; ks++) {
        float4 t = sp[(size_t)ks * (B * N160 / 4) + idx];
        s.x += t.x; s.y += t.y; s.z += t.z; s.w += t.w;
    }
    float4 v;
    v.x = s.x * fabsf(s.x) / (1.0f + s.x * s.x);
    v.y = s.y * fabsf(s.y) / (1.0f + s.y * s.y);
    v.z = s.z * fabsf(s.z) / (1.0f + s.z * s.z);
    v.w = s.w * fabsf(s.w) / (1.0f + s.w * s.w);
    ((float4*)g_v)[idx] = v;
    if (out) ((float4*)out)[idx] = v;
}

// Agreement fused: G[m=(r,i)][n=(c,o)] = sum_b xT[m][b]*v[b][n], then
// g_b[r,c] += (1/B) * sum_{i,o} G * W[r,c,o,i].
// tile 128(m) x 32(n), 128 threads, 8x4 per thread via FFMA2. grid (72, 5).
__global__ void __launch_bounds__(128) gemm2_k(const float* __restrict__ W) {
    const int m0 = blockIdx.x * 128, n0 = blockIdx.y * 32;
    const int tid = threadIdx.x;
    const int tn = tid & 7, tm = tid >> 3;

    __shared__ float as[16][132];  // [kk=b][m], padded
    __shared__ float vs[16][32];
    u64 acc2[4][4];
#pragma unroll
    for (int p = 0; p < 4; p++)
#pragma unroll
        for (int l = 0; l < 4; l++) acc2[p][l] = 0ull;

    for (int step = 0; step < B / 16; step++) {
        const int bb = step * 16;
#pragma unroll
        for (int j = 0; j < 4; j++) {
            int idx4 = tid + j * 128;          // 0..511
            int ml = idx4 >> 2, kk4 = idx4 & 3;
            float4 v4 = *(const float4*)(g_xT + (size_t)(m0 + ml) * B + bb + kk4 * 4);
            as[kk4 * 4 + 0][ml] = v4.x;
            as[kk4 * 4 + 1][ml] = v4.y;
            as[kk4 * 4 + 2][ml] = v4.z;
            as[kk4 * 4 + 3][ml] = v4.w;
        }
        {
            int row = tid >> 3, col4 = tid & 7;
            *(float4*)&vs[row][col4 * 4] =
                *(const float4*)(g_v + (size_t)(bb + row) * N160 + n0 + col4 * 4);
        }
        __syncthreads();
#pragma unroll
        for (int kk = 0; kk < 16; kk++) {
            float4 x0 = *(float4*)&as[kk][tm * 8];
            float4 x1 = *(float4*)&as[kk][tm * 8 + 4];
            float4 w0 = *(float4*)&vs[kk][tn * 4];
            u64 xp[4] = {pk(x0.x, x0.y), pk(x0.z, x0.w),
                         pk(x1.x, x1.y), pk(x1.z, x1.w)};
            u64 wr[4] = {pk1(w0.x), pk1(w0.y), pk1(w0.z), pk1(w0.w)};
#pragma unroll
            for (int p = 0; p < 4; p++)
#pragma unroll
                for (int l = 0; l < 4; l++)
                    fma2(acc2[p][l], xp[p], wr[l]);
        }
        __syncthreads();
    }

    // Unpack accumulators: acc[j][l], j over i (0..7), l over o (4 within c).
    float acc[8][4];
#pragma unroll
    for (int p = 0; p < 4; p++)
#pragma unroll
        for (int l = 0; l < 4; l++) {
            float2 t = up(acc2[p][l]);
            acc[2 * p][l] = t.x;
            acc[2 * p + 1][l] = t.y;
        }

    // Epilogue: each thread's 8 m span exactly one r (i = 0..7), 4 n within one c.
    const int r = (m0 >> 3) + tm;            // m0 + tm*8 -> r, i=j
    const int nb = n0 + tn * 4;
    const int c = nb >> 4, o0 = nb & 15;
    const float* wrc = W + ((size_t)(r * C + c) * O) * I;
    float part = 0.0f;
#pragma unroll
    for (int j = 0; j < 8; j++)
#pragma unroll
        for (int l = 0; l < 4; l++)
            part = fmaf(acc[j][l], wrc[(o0 + l) * I + j], part);

    __shared__ float red[32][4];
    const int slot = tm * 2 + (tn >> 2);     // (r_local, c_local) -> 0..31
    red[slot][tn & 3] = part;
    __syncthreads();
    if (tid < 32) {
        float s = red[tid][0] + red[tid][1] + red[tid][2] + red[tid][3];
        int rr = (m0 >> 3) + (tid >> 1);
        int cc = (n0 >> 4) + (tid & 1);
        g_b[rr * C + cc] += s * (1.0f / (float)B);
    }
}

extern "C" void kernel_launch(void* const* d_in, const int* in_sizes, int n_in,
                              void* d_out, int out_size) {
    const float* x = (const float*)d_in[0];
    const float* W = (const float*)d_in[1];
    if (n_in >= 2 && in_sizes[0] == R * C * O * I) {
        x = (const float*)d_in[1];
        W = (const float*)d_in[0];
    }

    init_k<<<(R * C + 255) / 256, 256>>>();
    transpose_k<<<dim3(K9 / 32, B / 32), dim3(32, 8)>>>(x);

    for (int it = 0; it < 3; it++) {
        if (it > 0) softmax_k<<<C, 128>>>();
        scale_k<<<R, 256>>>(W, it == 0 ? 1 : 0);
        gemm1_k<<<dim3(B / 128, N160 / 32, NKS), 128>>>();
        squash_k<<<(B * N160 / 4) / 256, 256>>>(it == 2 ? (float*)d_out : nullptr);
        if (it < 2) gemm2_k<<<dim3(K9 / 128, N160 / 32), 128>>>(W);
    }
}